// round 17
// baseline (speedup 1.0000x reference)
#include <cuda_runtime.h>

#define N_NODES 50000
#define N_EDGES 600000
#define REL_NUM 500
#define E_HID   128

#define SCAN_B   1024
#define SCAN_NB  ((N_NODES + SCAN_B - 1) / SCAN_B)   // 49

#define DP_BLK    256
#define DP_WARPS  (DP_BLK / 32)
#define DP_NB     ((N_NODES + DP_WARPS - 1) / DP_WARPS)  // 6250

#define REL_BLKS  (REL_NUM / 2)    // 250 blocks, 2 rel rows each
#define PREP_GRID (REL_BLKS + 1024)

// output layout: x_e [50000*128] | rel_out [500*128] | res_att [600000]
#define REL_OFF (N_NODES * E_HID)
#define RES_OFF (REL_OFF + REL_NUM * E_HID)

// scratch (device globals: no allocations allowed; zero-initialized at load)
__device__ float g_remb[REL_NUM * E_HID];  // r_emb = rel_emb @ ww_w.T
__device__ int   g_pack[N_EDGES];          // (rel<<17)|src, CSR order
__device__ int   g_cnt[N_NODES];           // in-degree histogram (re-zeroed by scan_c)
__device__ int   g_row[N_NODES + 1];       // CSR row offsets
__device__ int   g_cur[N_NODES];           // fill cursors
__device__ int   g_bsum[SCAN_NB];
__device__ float g_nm[N_NODES];            // per-node running max m_n
__device__ float g_pmax[DP_NB];            // per-block softmax partials
__device__ float g_psum[DP_NB];
__device__ float g_m;                      // global max
__device__ float g_inv;                    // 1 / global sum

// warp-wide reductions (shfl butterfly; redux.f32 not on sm_103)
__device__ __forceinline__ float warp_sum(float v) {
#pragma unroll
    for (int o = 16; o; o >>= 1) v += __shfl_xor_sync(0xffffffffu, v, o);
    return v;
}
__device__ __forceinline__ int warp_sum_i(int v) {
#pragma unroll
    for (int o = 16; o; o >>= 1) v += __shfl_xor_sync(0xffffffffu, v, o);
    return v;
}

// ---------------------------------------------------------------------------
// K_PREP: heterogeneous merge of rel-GEMMs + res_att copy + dst histogram.
// blocks [0, REL_BLKS): 2 rel rows each (256 thr = 2 x 128).
// blocks [REL_BLKS, ...): grid-stride copy res_att + atomic histogram.
// g_cnt arrives zeroed (static init on call 1; scan_c re-zeroes thereafter).
// ---------------------------------------------------------------------------
__global__ void k_prep(float* __restrict__ out, const float* __restrict__ res_att,
                       const float* __restrict__ rel_emb,
                       const float* __restrict__ ww_w,
                       const float* __restrict__ rel_w,
                       const int* __restrict__ ei) {
    if (blockIdx.x < REL_BLKS) {
        __shared__ float row[2][E_HID];
        int half = threadIdx.x >> 7;          // 0 or 1
        int t = threadIdx.x & 127;
        int r = blockIdx.x * 2 + half;
        row[half][t] = rel_emb[r * E_HID + t];
        __syncthreads();
        float a = 0.f, b = 0.f;
#pragma unroll 8
        for (int k = 0; k < E_HID; k++) {
            float v = row[half][k];
            a = fmaf(v, ww_w[t * E_HID + k], a);
            b = fmaf(v, rel_w[t * E_HID + k], b);
        }
        g_remb[r * E_HID + t] = a;
        out[REL_OFF + r * E_HID + t] = b;
    } else {
        int i = (blockIdx.x - REL_BLKS) * blockDim.x + threadIdx.x;
        int stride = (gridDim.x - REL_BLKS) * blockDim.x;
        for (int e = i; e < N_EDGES; e += stride) {
            out[RES_OFF + e] = res_att[e];
            atomicAdd(&g_cnt[ei[N_EDGES + e]], 1);
        }
    }
}

// ---------------------------------------------------------------------------
// K_SCAN_A: per-block exclusive scan (49 x 1024); write block totals
// ---------------------------------------------------------------------------
__global__ void k_scan_a() {
    __shared__ int warp_sums[32];
    int t = threadIdx.x;
    int lane = t & 31, w = t >> 5;
    int idx = blockIdx.x * SCAN_B + t;
    int v = (idx < N_NODES) ? g_cnt[idx] : 0;
    int xv = v;
#pragma unroll
    for (int o = 1; o < 32; o <<= 1) {
        int y = __shfl_up_sync(0xffffffffu, xv, o);
        if (lane >= o) xv += y;
    }
    if (lane == 31) warp_sums[w] = xv;
    __syncthreads();
    if (w == 0) {
        int ws = warp_sums[lane];
#pragma unroll
        for (int o = 1; o < 32; o <<= 1) {
            int y = __shfl_up_sync(0xffffffffu, ws, o);
            if (lane >= o) ws += y;
        }
        warp_sums[lane] = ws;
    }
    __syncthreads();
    int excl = xv - v + (w > 0 ? warp_sums[w - 1] : 0);
    if (idx < N_NODES) g_row[idx] = excl;
    if (t == SCAN_B - 1) g_bsum[blockIdx.x] = excl + v;
}

// ---------------------------------------------------------------------------
// K_SCAN_C: each block computes its own offset from g_bsum (redundant tiny
// reduce; replaces scan_b), applies it, mirrors into g_cur, re-zeroes g_cnt.
// ---------------------------------------------------------------------------
__global__ void k_scan_c() {
    __shared__ int wred[2];
    __shared__ int sboff;
    int t = threadIdx.x;
    if (t < 64) {
        int v = (t < blockIdx.x) ? g_bsum[t] : 0;   // SCAN_NB=49 <= 64
        int s = warp_sum_i(v);
        if ((t & 31) == 0) wred[t >> 5] = s;
    }
    __syncthreads();
    if (t == 0) sboff = wred[0] + wred[1];
    __syncthreads();
    int idx = blockIdx.x * SCAN_B + t;
    if (idx < N_NODES) {
        int r = g_row[idx] + sboff;
        g_row[idx] = r;
        g_cur[idx] = r;
        g_cnt[idx] = 0;                 // reset histogram for next call
    }
    if (idx == 0) g_row[N_NODES] = N_EDGES;
}

// ---------------------------------------------------------------------------
// K_FILL: packed CSR payload: (rel<<17)|src per slot, grouped by dst
// ---------------------------------------------------------------------------
__global__ void k_fill(const int* __restrict__ ei, const int* __restrict__ et) {
    int i = blockIdx.x * blockDim.x + threadIdx.x;
    int stride = gridDim.x * blockDim.x;
    for (int e = i; e < N_EDGES; e += stride) {
        int dst = ei[N_EDGES + e];
        int pos = atomicAdd(&g_cur[dst], 1);
        g_pack[pos] = ei[e] | (et[e] << 17);
    }
}

// ---------------------------------------------------------------------------
// K_FUSED: R13 batch-4 form (validated fastest), + launch_bounds for
// 4 blocks/SM (more resident warps -> more outstanding gathers).
// ---------------------------------------------------------------------------
__global__ void __launch_bounds__(DP_BLK, 4)
k_fused(const float* __restrict__ x, float* __restrict__ out) {
    __shared__ float sm_m[DP_WARPS], sm_s[DP_WARPS];
    int n = (int)(((long long)blockIdx.x * blockDim.x + threadIdx.x) >> 5);
    int lane = threadIdx.x & 31;
    int w = threadIdx.x >> 5;

    float m_w = -3.4e38f, s_w = 0.f;
    if (n < N_NODES) {
        int beg = g_row[n], end = g_row[n + 1];
        const float4 xd = *(const float4*)(x + (long long)n * E_HID + lane * 4);
        float ax = 0.f, ay = 0.f, az = 0.f, aw = 0.f;

        int i = beg;
        for (; i + 4 <= end; i += 4) {
            int pk0 = g_pack[i + 0], pk1 = g_pack[i + 1];
            int pk2 = g_pack[i + 2], pk3 = g_pack[i + 3];
            const float4 a0 = *(const float4*)(x + (long long)(pk0 & 0x1FFFF) * E_HID + lane * 4);
            const float4 b0 = *(const float4*)(g_remb + (long long)(pk0 >> 17) * E_HID + lane * 4);
            const float4 a1 = *(const float4*)(x + (long long)(pk1 & 0x1FFFF) * E_HID + lane * 4);
            const float4 b1 = *(const float4*)(g_remb + (long long)(pk1 >> 17) * E_HID + lane * 4);
            const float4 a2 = *(const float4*)(x + (long long)(pk2 & 0x1FFFF) * E_HID + lane * 4);
            const float4 b2 = *(const float4*)(g_remb + (long long)(pk2 >> 17) * E_HID + lane * 4);
            const float4 a3 = *(const float4*)(x + (long long)(pk3 & 0x1FFFF) * E_HID + lane * 4);
            const float4 b3 = *(const float4*)(g_remb + (long long)(pk3 >> 17) * E_HID + lane * 4);

            float h0x = a0.x + b0.x, h0y = a0.y + b0.y, h0z = a0.z + b0.z, h0w = a0.w + b0.w;
            float h1x = a1.x + b1.x, h1y = a1.y + b1.y, h1z = a1.z + b1.z, h1w = a1.w + b1.w;
            float h2x = a2.x + b2.x, h2y = a2.y + b2.y, h2z = a2.z + b2.z, h2w = a2.w + b2.w;
            float h3x = a3.x + b3.x, h3y = a3.y + b3.y, h3z = a3.z + b3.z, h3w = a3.w + b3.w;

            float p0 = h0x * xd.x + h0y * xd.y + h0z * xd.z + h0w * xd.w;
            float p1 = h1x * xd.x + h1y * xd.y + h1z * xd.z + h1w * xd.w;
            float p2 = h2x * xd.x + h2y * xd.y + h2z * xd.z + h2w * xd.w;
            float p3 = h3x * xd.x + h3y * xd.y + h3z * xd.z + h3w * xd.w;
#pragma unroll
            for (int o = 16; o; o >>= 1) {
                p0 += __shfl_xor_sync(0xffffffffu, p0, o);
                p1 += __shfl_xor_sync(0xffffffffu, p1, o);
                p2 += __shfl_xor_sync(0xffffffffu, p2, o);
                p3 += __shfl_xor_sync(0xffffffffu, p3, o);
            }

            float mb = fmaxf(fmaxf(p0, p1), fmaxf(p2, p3));
            float m2 = fmaxf(m_w, mb);
            float sc = __expf(m_w - m2);        // 1.0 when max unchanged
            float c0 = __expf(p0 - m2), c1 = __expf(p1 - m2);
            float c2 = __expf(p2 - m2), c3 = __expf(p3 - m2);
            s_w = s_w * sc + ((c0 + c1) + (c2 + c3));
            ax = fmaf(c3, h3x, fmaf(c2, h2x, fmaf(c1, h1x, fmaf(c0, h0x, ax * sc))));
            ay = fmaf(c3, h3y, fmaf(c2, h2y, fmaf(c1, h1y, fmaf(c0, h0y, ay * sc))));
            az = fmaf(c3, h3z, fmaf(c2, h2z, fmaf(c1, h1z, fmaf(c0, h0z, az * sc))));
            aw = fmaf(c3, h3w, fmaf(c2, h2w, fmaf(c1, h1w, fmaf(c0, h0w, aw * sc))));
            m_w = m2;
        }
        // remainder (0-3 edges), scalar online softmax
        for (; i < end; i++) {
            int pk = g_pack[i];
            const float4 xs = *(const float4*)(x + (long long)(pk & 0x1FFFF) * E_HID + lane * 4);
            const float4 rr = *(const float4*)(g_remb + (long long)(pk >> 17) * E_HID + lane * 4);
            float hx = xs.x + rr.x, hy = xs.y + rr.y;
            float hz = xs.z + rr.z, hw = xs.w + rr.w;
            float p = warp_sum(hx * xd.x + hy * xd.y + hz * xd.z + hw * xd.w);
            float m2 = fmaxf(m_w, p);
            float sc = __expf(m_w - m2);
            float c = __expf(p - m2);
            s_w = s_w * sc + c;
            ax = fmaf(c, hx, ax * sc);
            ay = fmaf(c, hy, ay * sc);
            az = fmaf(c, hz, az * sc);
            aw = fmaf(c, hw, aw * sc);
            m_w = m2;
        }
        float4* o = (float4*)(out + (long long)n * E_HID) + lane;
        *o = make_float4(ax, ay, az, aw);     // unnormalized
        if (lane == 0) g_nm[n] = m_w;
    }
    if (lane == 0) { sm_m[w] = m_w; sm_s[w] = s_w; }
    __syncthreads();
    if (threadIdx.x == 0) {
        float M = sm_m[0], S = sm_s[0];
#pragma unroll
        for (int k = 1; k < DP_WARPS; k++) {
            float m2 = sm_m[k], s2 = sm_s[k];
            float M2 = fmaxf(M, m2);
            S = S * __expf(M - M2) + s2 * __expf(m2 - M2);
            M = M2;
        }
        g_pmax[blockIdx.x] = M;
        g_psum[blockIdx.x] = S;
    }
}

// ---------------------------------------------------------------------------
// K_COMBINE: merge per-block (m, s) partials -> g_m, g_inv. Single block.
// ---------------------------------------------------------------------------
__global__ void k_combine() {
    __shared__ float sm_m[32], sm_s[32];
    int t = threadIdx.x;             // 1024
    int lane = t & 31, w = t >> 5;
    float M = -3.4e38f, S = 0.f;
    for (int i = t; i < DP_NB; i += 1024) {
        float m2 = g_pmax[i], s2 = g_psum[i];
        float M2 = fmaxf(M, m2);
        S = S * __expf(M - M2) + s2 * __expf(m2 - M2);
        M = M2;
    }
#pragma unroll
    for (int o = 16; o; o >>= 1) {
        float m2 = __shfl_xor_sync(0xffffffffu, M, o);
        float s2 = __shfl_xor_sync(0xffffffffu, S, o);
        float M2 = fmaxf(M, m2);
        S = S * __expf(M - M2) + s2 * __expf(m2 - M2);
        M = M2;
    }
    if (lane == 0) { sm_m[w] = M; sm_s[w] = S; }
    __syncthreads();
    if (t == 0) {
        M = sm_m[0]; S = sm_s[0];
#pragma unroll
        for (int k = 1; k < 32; k++) {
            float m2 = sm_m[k], s2 = sm_s[k];
            float M2 = fmaxf(M, m2);
            S = S * __expf(M - M2) + s2 * __expf(m2 - M2);
            M = M2;
        }
        g_m = M;
        g_inv = 1.0f / S;
    }
}

// ---------------------------------------------------------------------------
// K_SCALE: out[n,:] *= exp(m_n - M) / S, then ReLU. Streaming 51MB.
// ---------------------------------------------------------------------------
__global__ void k_scale(float* __restrict__ out) {
    int n = (int)(((long long)blockIdx.x * blockDim.x + threadIdx.x) >> 5);
    int lane = threadIdx.x & 31;
    if (n >= N_NODES) return;
    float sc = __expf(g_nm[n] - g_m) * g_inv;
    float4* o = (float4*)(out + (long long)n * E_HID) + lane;
    float4 v = *o;
    *o = make_float4(fmaxf(v.x * sc, 0.f), fmaxf(v.y * sc, 0.f),
                     fmaxf(v.z * sc, 0.f), fmaxf(v.w * sc, 0.f));
}

extern "C" void kernel_launch(void* const* d_in, const int* in_sizes, int n_in,
                              void* d_out, int out_size) {
    const float* x       = (const float*)d_in[0];   // [50000,128] f32
    const int*   ei      = (const int*)d_in[1];     // [2,600000] int32
    const int*   et      = (const int*)d_in[2];     // [600000] int32
    const float* rel_emb = (const float*)d_in[3];   // [500,128]
    const float* res_att = (const float*)d_in[4];   // [600000]
    const float* ww_w    = (const float*)d_in[5];   // [128,128]
    const float* rel_w   = (const float*)d_in[6];   // [128,128]
    float* out = (float*)d_out;

    (void)in_sizes; (void)n_in; (void)out_size;

    // merged prep: rel GEMMs + res_att copy + dst histogram
    k_prep<<<PREP_GRID, 256>>>(out, res_att, rel_emb, ww_w, rel_w, ei);

    // CSR-by-dst: scan (2 launches; scan_b folded into scan_c) + fill
    k_scan_a<<<SCAN_NB, SCAN_B>>>();
    k_scan_c<<<SCAN_NB, SCAN_B>>>();
    k_fill<<<1024, 256>>>(ei, et);

    // single fused gather pass (batch-4 edges, default cache policy)
    k_fused<<<DP_NB, DP_BLK>>>(x, out);
    k_combine<<<1, 1024>>>();
    k_scale<<<DP_NB, DP_BLK>>>(out);
}